// round 15
// baseline (speedup 1.0000x reference)
#include <cuda_runtime.h>
#include <cstdint>

#define MAX_NODES 100000
#define F1 32
#define F2 16
#define F3 2
#define CAP 64   // max in-degree bucket capacity (Poisson(16): P(>64) ~ 1e-20)

// Scratch (device globals; no allocation allowed)
__device__ __align__(256) float g_y1[MAX_NODES * F1];
__device__ __align__(256) float g_h1[MAX_NODES * F1];
__device__ __align__(256) float g_y2[MAX_NODES * F2];
__device__ __align__(256) float g_h2[MAX_NODES * F2];
__device__ __align__(256) float g_y3[MAX_NODES * F3];
__device__ __align__(256) float g_h3[MAX_NODES * F3];
__device__ __align__(256) int   g_cnt[MAX_NODES];         // in-degree counters
__device__ __align__(256) int   g_slots[MAX_NODES * CAP]; // per-dst src buckets

// ---- PDL device controls ----
__device__ __forceinline__ void pdl_wait()    { asm volatile("griddepcontrol.wait;" ::: "memory"); }
__device__ __forceinline__ void pdl_trigger() { asm volatile("griddepcontrol.launch_dependents;" ::: "memory"); }

// ---- packed f32x2 helpers ----
__device__ __forceinline__ unsigned long long pack2(float lo, float hi) {
    unsigned long long r;
    asm("mov.b64 %0, {%1, %2};" : "=l"(r) : "f"(lo), "f"(hi));
    return r;
}
__device__ __forceinline__ void unpack2(unsigned long long v, float& lo, float& hi) {
    asm("mov.b64 {%0, %1}, %2;" : "=f"(lo), "=f"(hi) : "l"(v));
}
__device__ __forceinline__ unsigned long long ffma2(
    unsigned long long a, unsigned long long b, unsigned long long c) {
    unsigned long long d;
    asm("fma.rn.f32x2 %0, %1, %2, %3;" : "=l"(d) : "l"(a), "l"(b), "l"(c));
    return d;
}

// ---------------------------------------------------------------------------
// Bucket build (runs on side stream, parallel to transform1).
// ---------------------------------------------------------------------------
__global__ void zero_k(int* __restrict__ cnt, int n) {
    int i = blockIdx.x * blockDim.x + threadIdx.x;
    if (i < n) cnt[i] = 0;
}

__global__ void fill_k(const int* __restrict__ ei, int* __restrict__ cnt,
                       int* __restrict__ slots, int e) {
    int pe = blockIdx.x * blockDim.x + threadIdx.x;
    int base = 4 * pe;
    if (base >= e) return;

    int src[4], dst[4];
    if (base + 3 < e) {
        int4 s4 = __ldg(reinterpret_cast<const int4*>(ei) + pe);
        int4 d4 = __ldg(reinterpret_cast<const int4*>(ei + e) + pe);
        src[0] = s4.x; src[1] = s4.y; src[2] = s4.z; src[3] = s4.w;
        dst[0] = d4.x; dst[1] = d4.y; dst[2] = d4.z; dst[3] = d4.w;
    } else {
#pragma unroll
        for (int i = 0; i < 4; i++) {
            int eid = base + i;
            bool ok = eid < e;
            src[i] = ok ? __ldg(ei + eid) : 0;
            dst[i] = ok ? __ldg(ei + e + eid) : -1;
        }
    }
#pragma unroll
    for (int i = 0; i < 4; i++) {
        if (base + i < e && dst[i] >= 0) {
            int pos = atomicAdd(&cnt[dst[i]], 1);
            if (pos < CAP) slots[dst[i] * CAP + pos] = src[i];
        }
    }
}

// ---------------------------------------------------------------------------
// Dense transform (R13 exact): y = act(x)@Wrel ; h = act(x)@Wroot + b.
// ---------------------------------------------------------------------------
template <int FIN, int FOUT, bool RELU>
__global__ void transform_k(const float* __restrict__ x,
                            const float* __restrict__ Wrel,
                            const float* __restrict__ Wroot,
                            const float* __restrict__ b,
                            float* __restrict__ y,
                            float* __restrict__ h,
                            int n) {
    __shared__ __align__(16) float s_rel[FIN * FOUT];
    __shared__ __align__(16) float s_root[FIN * FOUT];
    __shared__ float s_b[FOUT];
    for (int i = threadIdx.x; i < FIN * FOUT; i += blockDim.x) {
        s_rel[i]  = Wrel[i];
        s_root[i] = Wroot[i];
    }
    for (int i = threadIdx.x; i < FOUT; i += blockDim.x) s_b[i] = b[i];
    __syncthreads();

    pdl_wait();

    int node = blockIdx.x * blockDim.x + threadIdx.x;
    if (node >= n) { pdl_trigger(); return; }

    constexpr int P = FOUT / 2;
    unsigned long long accR[P], accO[P];
#pragma unroll
    for (int p = 0; p < P; p++) { accR[p] = 0ull; accO[p] = 0ull; }

    const float4* xr = reinterpret_cast<const float4*>(x + (size_t)node * FIN);
#pragma unroll
    for (int kk = 0; kk < FIN / 4; kk++) {
        float4 xv = __ldg(xr + kk);
        float xs[4] = {xv.x, xv.y, xv.z, xv.w};
#pragma unroll
        for (int q = 0; q < 4; q++) {
            float v = RELU ? fmaxf(xs[q], 0.f) : xs[q];
            unsigned long long a = pack2(v, v);
            const int k = kk * 4 + q;
            if constexpr (FOUT >= 4) {
#pragma unroll
                for (int j4 = 0; j4 < FOUT / 4; j4++) {
                    ulonglong2 wr = *reinterpret_cast<const ulonglong2*>(&s_rel[k * FOUT + j4 * 4]);
                    ulonglong2 wo = *reinterpret_cast<const ulonglong2*>(&s_root[k * FOUT + j4 * 4]);
                    accR[j4 * 2 + 0] = ffma2(a, wr.x, accR[j4 * 2 + 0]);
                    accR[j4 * 2 + 1] = ffma2(a, wr.y, accR[j4 * 2 + 1]);
                    accO[j4 * 2 + 0] = ffma2(a, wo.x, accO[j4 * 2 + 0]);
                    accO[j4 * 2 + 1] = ffma2(a, wo.y, accO[j4 * 2 + 1]);
                }
            } else {
                unsigned long long wr = *reinterpret_cast<const unsigned long long*>(&s_rel[k * FOUT]);
                unsigned long long wo = *reinterpret_cast<const unsigned long long*>(&s_root[k * FOUT]);
                accR[0] = ffma2(a, wr, accR[0]);
                accO[0] = ffma2(a, wo, accO[0]);
            }
        }
    }

    float* yo = y + (size_t)node * FOUT;
    float* ho = h + (size_t)node * FOUT;
    float outR[FOUT], outO[FOUT];
#pragma unroll
    for (int p = 0; p < P; p++) {
        unpack2(accR[p], outR[2 * p], outR[2 * p + 1]);
        unpack2(accO[p], outO[2 * p], outO[2 * p + 1]);
    }
    if constexpr (FOUT >= 4) {
#pragma unroll
        for (int j4 = 0; j4 < FOUT / 4; j4++) {
            reinterpret_cast<float4*>(yo)[j4] =
                make_float4(outR[j4 * 4], outR[j4 * 4 + 1], outR[j4 * 4 + 2], outR[j4 * 4 + 3]);
            reinterpret_cast<float4*>(ho)[j4] =
                make_float4(outO[j4 * 4] + s_b[j4 * 4],         outO[j4 * 4 + 1] + s_b[j4 * 4 + 1],
                            outO[j4 * 4 + 2] + s_b[j4 * 4 + 2], outO[j4 * 4 + 3] + s_b[j4 * 4 + 3]);
        }
    } else {
        *reinterpret_cast<float2*>(yo) = make_float2(outR[0], outR[1]);
        *reinterpret_cast<float2*>(ho) = make_float2(outO[0] + s_b[0], outO[1] + s_b[1]);
    }
    pdl_trigger();
}

// ---------------------------------------------------------------------------
// Pull aggregation: thread per (node, float4-chunk), 8 gathers in flight.
// Slot rows are 256B-aligned (CAP*4), so 8 ids = two int4 loads.
// ---------------------------------------------------------------------------
template <int F>
__global__ void agg_k(const int* __restrict__ cnt, const int* __restrict__ slots,
                      const float* __restrict__ y, float* __restrict__ h, int n) {
    constexpr int CH = F / 4;
    pdl_wait();
    int t = blockIdx.x * blockDim.x + threadIdx.x;
    if (t >= n * CH) { pdl_trigger(); return; }
    int node = t / CH;
    int c = t % CH;
    int deg = min(__ldg(cnt + node), CAP);
    const int* sl = slots + node * CAP;

    float4 a0 = make_float4(0.f, 0.f, 0.f, 0.f);
    float4 a1 = a0, a2 = a0, a3 = a0;
    int i = 0;
    for (; i + 8 <= deg; i += 8) {
        int4 q0 = __ldg(reinterpret_cast<const int4*>(sl + i));
        int4 q1 = __ldg(reinterpret_cast<const int4*>(sl + i + 4));
        float4 v0 = __ldg(reinterpret_cast<const float4*>(y + (size_t)q0.x * F + c * 4));
        float4 v1 = __ldg(reinterpret_cast<const float4*>(y + (size_t)q0.y * F + c * 4));
        float4 v2 = __ldg(reinterpret_cast<const float4*>(y + (size_t)q0.z * F + c * 4));
        float4 v3 = __ldg(reinterpret_cast<const float4*>(y + (size_t)q0.w * F + c * 4));
        float4 v4 = __ldg(reinterpret_cast<const float4*>(y + (size_t)q1.x * F + c * 4));
        float4 v5 = __ldg(reinterpret_cast<const float4*>(y + (size_t)q1.y * F + c * 4));
        float4 v6 = __ldg(reinterpret_cast<const float4*>(y + (size_t)q1.z * F + c * 4));
        float4 v7 = __ldg(reinterpret_cast<const float4*>(y + (size_t)q1.w * F + c * 4));
        a0.x += v0.x; a0.y += v0.y; a0.z += v0.z; a0.w += v0.w;
        a1.x += v1.x; a1.y += v1.y; a1.z += v1.z; a1.w += v1.w;
        a2.x += v2.x; a2.y += v2.y; a2.z += v2.z; a2.w += v2.w;
        a3.x += v3.x; a3.y += v3.y; a3.z += v3.z; a3.w += v3.w;
        a0.x += v4.x; a0.y += v4.y; a0.z += v4.z; a0.w += v4.w;
        a1.x += v5.x; a1.y += v5.y; a1.z += v5.z; a1.w += v5.w;
        a2.x += v6.x; a2.y += v6.y; a2.z += v6.z; a2.w += v6.w;
        a3.x += v7.x; a3.y += v7.y; a3.z += v7.z; a3.w += v7.w;
    }
    for (; i + 4 <= deg; i += 4) {
        int4 q0 = __ldg(reinterpret_cast<const int4*>(sl + i));
        float4 v0 = __ldg(reinterpret_cast<const float4*>(y + (size_t)q0.x * F + c * 4));
        float4 v1 = __ldg(reinterpret_cast<const float4*>(y + (size_t)q0.y * F + c * 4));
        float4 v2 = __ldg(reinterpret_cast<const float4*>(y + (size_t)q0.z * F + c * 4));
        float4 v3 = __ldg(reinterpret_cast<const float4*>(y + (size_t)q0.w * F + c * 4));
        a0.x += v0.x; a0.y += v0.y; a0.z += v0.z; a0.w += v0.w;
        a1.x += v1.x; a1.y += v1.y; a1.z += v1.z; a1.w += v1.w;
        a2.x += v2.x; a2.y += v2.y; a2.z += v2.z; a2.w += v2.w;
        a3.x += v3.x; a3.y += v3.y; a3.z += v3.z; a3.w += v3.w;
    }
    for (; i < deg; i++) {
        int s = __ldg(sl + i);
        float4 v = __ldg(reinterpret_cast<const float4*>(y + (size_t)s * F + c * 4));
        a0.x += v.x; a0.y += v.y; a0.z += v.z; a0.w += v.w;
    }
    float4 acc = make_float4(a0.x + a1.x + a2.x + a3.x,
                             a0.y + a1.y + a2.y + a3.y,
                             a0.z + a1.z + a2.z + a3.z,
                             a0.w + a1.w + a2.w + a3.w);
    float4* hp = reinterpret_cast<float4*>(h + (size_t)node * F) + c;
    float4 r = *hp;
    r.x += acc.x; r.y += acc.y; r.z += acc.z; r.w += acc.w;
    *hp = r;
    pdl_trigger();
}

// Layer-3 pull aggregation (F=2) fused with 2-class softmax. One thread/node.
__global__ void agg3_softmax_k(const int* __restrict__ cnt, const int* __restrict__ slots,
                               const float* __restrict__ y, const float* __restrict__ h,
                               float* __restrict__ out, int n) {
    pdl_wait();
    int node = blockIdx.x * blockDim.x + threadIdx.x;
    if (node >= n) return;
    int deg = min(__ldg(cnt + node), CAP);
    const int* sl = slots + node * CAP;

    float ax0 = 0.f, ay0 = 0.f, ax1 = 0.f, ay1 = 0.f;
    float ax2 = 0.f, ay2 = 0.f, ax3 = 0.f, ay3 = 0.f;
    int i = 0;
    for (; i + 8 <= deg; i += 8) {
        int4 q0 = __ldg(reinterpret_cast<const int4*>(sl + i));
        int4 q1 = __ldg(reinterpret_cast<const int4*>(sl + i + 4));
        float2 v0 = __ldg(reinterpret_cast<const float2*>(y + 2 * (size_t)q0.x));
        float2 v1 = __ldg(reinterpret_cast<const float2*>(y + 2 * (size_t)q0.y));
        float2 v2 = __ldg(reinterpret_cast<const float2*>(y + 2 * (size_t)q0.z));
        float2 v3 = __ldg(reinterpret_cast<const float2*>(y + 2 * (size_t)q0.w));
        float2 v4 = __ldg(reinterpret_cast<const float2*>(y + 2 * (size_t)q1.x));
        float2 v5 = __ldg(reinterpret_cast<const float2*>(y + 2 * (size_t)q1.y));
        float2 v6 = __ldg(reinterpret_cast<const float2*>(y + 2 * (size_t)q1.z));
        float2 v7 = __ldg(reinterpret_cast<const float2*>(y + 2 * (size_t)q1.w));
        ax0 += v0.x; ay0 += v0.y;  ax1 += v1.x; ay1 += v1.y;
        ax2 += v2.x; ay2 += v2.y;  ax3 += v3.x; ay3 += v3.y;
        ax0 += v4.x; ay0 += v4.y;  ax1 += v5.x; ay1 += v5.y;
        ax2 += v6.x; ay2 += v6.y;  ax3 += v7.x; ay3 += v7.y;
    }
    for (; i < deg; i++) {
        int s = __ldg(sl + i);
        float2 v = __ldg(reinterpret_cast<const float2*>(y + 2 * (size_t)s));
        ax0 += v.x; ay0 += v.y;
    }
    float ax = (ax0 + ax1) + (ax2 + ax3);
    float ay = (ay0 + ay1) + (ay2 + ay3);

    float2 r = *reinterpret_cast<const float2*>(h + 2 * (size_t)node);
    float vx = r.x + ax, vy = r.y + ay;
    float m  = fmaxf(vx, vy);
    float ea = __expf(vx - m);
    float eb = __expf(vy - m);
    float inv = 1.0f / (ea + eb);
    reinterpret_cast<float2*>(out)[node] = make_float2(ea * inv, eb * inv);
}

// ---------------------------------------------------------------------------
// Host: forked graph — bucket build on side stream, main chain PDL-linked.
// ---------------------------------------------------------------------------
static void launch_one(cudaStream_t st, const void* fn, int grid, int block,
                       void** args, bool pdl) {
    cudaLaunchConfig_t cfg = {};
    cfg.gridDim = dim3((unsigned)grid, 1, 1);
    cfg.blockDim = dim3((unsigned)block, 1, 1);
    cfg.dynamicSmemBytes = 0;
    cfg.stream = st;
    cudaLaunchAttribute attr[1];
    if (pdl) {
        attr[0].id = cudaLaunchAttributeProgrammaticStreamSerialization;
        attr[0].val.programmaticStreamSerializationAllowed = 1;
        cfg.attrs = attr;
        cfg.numAttrs = 1;
    }
    cudaLaunchKernelExC(&cfg, fn, args);
}

extern "C" void kernel_launch(void* const* d_in, const int* in_sizes, int n_in,
                              void* d_out, int out_size) {
    const float* z      = (const float*)d_in[0];
    const int*   ei     = (const int*)d_in[1];   // int32 (JAX x64 disabled)
    const float* Wrel1  = (const float*)d_in[2];
    const float* Wroot1 = (const float*)d_in[3];
    const float* b1     = (const float*)d_in[4];
    const float* Wrel2  = (const float*)d_in[5];
    const float* Wroot2 = (const float*)d_in[6];
    const float* b2     = (const float*)d_in[7];
    const float* Wrel3  = (const float*)d_in[8];
    const float* Wroot3 = (const float*)d_in[9];
    const float* b3     = (const float*)d_in[10];

    int n = in_sizes[0] / 64;   // 100000
    int e = in_sizes[1] / 2;    // 1600000

    float *y1, *h1, *y2, *h2, *y3, *h3;
    int *cnt, *slots;
    cudaGetSymbolAddress((void**)&y1, g_y1);
    cudaGetSymbolAddress((void**)&h1, g_h1);
    cudaGetSymbolAddress((void**)&y2, g_y2);
    cudaGetSymbolAddress((void**)&h2, g_h2);
    cudaGetSymbolAddress((void**)&y3, g_y3);
    cudaGetSymbolAddress((void**)&h3, g_h3);
    cudaGetSymbolAddress((void**)&cnt, g_cnt);
    cudaGetSymbolAddress((void**)&slots, g_slots);

    // Lazily-created side stream + events (host objects only; no device mem)
    static cudaStream_t s2 = nullptr;
    static cudaEvent_t evFork = nullptr, evJoin = nullptr;
    if (!s2) {
        cudaStreamCreateWithFlags(&s2, cudaStreamNonBlocking);
        cudaEventCreateWithFlags(&evFork, cudaEventDisableTiming);
        cudaEventCreateWithFlags(&evJoin, cudaEventDisableTiming);
    }

    const int TB = 128;
    const int nodeBlocks = (n + TB - 1) / TB;
    const int eq = (e + 3) / 4;
    float* out = (float*)d_out;
    cudaStream_t s0 = 0;

    // Fork: bucket build on s2, transform1 on s0 (independent work).
    cudaEventRecord(evFork, s0);
    cudaStreamWaitEvent(s2, evFork, 0);
    {
        void* args[] = {&cnt, &n};
        launch_one(s2, (const void*)zero_k, (n + 255) / 256, 256, args, false);
    }
    {
        void* args[] = {&ei, &cnt, &slots, &e};
        launch_one(s2, (const void*)fill_k, (eq + 255) / 256, 256, args, false);
    }
    cudaEventRecord(evJoin, s2);

    {
        void* args[] = {&z, &Wrel1, &Wroot1, &b1, &y1, &h1, &n};
        launch_one(s0, (const void*)transform_k<64, F1, false>, nodeBlocks, TB, args, false);
    }
    // Join: agg1 needs both transform1 (s0) and fill (s2).
    cudaStreamWaitEvent(s0, evJoin, 0);
    {
        int blocks = (n * (F1 / 4) + 255) / 256;
        void* args[] = {&cnt, &slots, &y1, &h1, &n};
        launch_one(s0, (const void*)agg_k<F1>, blocks, 256, args, false);
    }
    // Layer 2
    {
        void* args[] = {&h1, &Wrel2, &Wroot2, &b2, &y2, &h2, &n};
        launch_one(s0, (const void*)transform_k<F1, F2, true>, nodeBlocks, TB, args, true);
    }
    {
        int blocks = (n * (F2 / 4) + 255) / 256;
        void* args[] = {&cnt, &slots, &y2, &h2, &n};
        launch_one(s0, (const void*)agg_k<F2>, blocks, 256, args, true);
    }
    // Layer 3 + fused softmax
    {
        void* args[] = {&h2, &Wrel3, &Wroot3, &b3, &y3, &h3, &n};
        launch_one(s0, (const void*)transform_k<F2, F3, true>, nodeBlocks, TB, args, true);
    }
    {
        void* args[] = {&cnt, &slots, &y3, &h3, &out, &n};
        launch_one(s0, (const void*)agg3_softmax_k, nodeBlocks, TB, args, true);
    }
}

// round 16
// speedup vs baseline: 1.0629x; 1.0629x over previous
#include <cuda_runtime.h>
#include <cstdint>

#define MAX_NODES 100000
#define F1 32
#define F2 16
#define F3 2
#define CAP 64   // max in-degree bucket capacity (Poisson(16): P(>64) ~ 1e-20)

// Scratch (device globals; no allocation allowed)
__device__ __align__(256) float g_y1[MAX_NODES * F1];
__device__ __align__(256) float g_h1[MAX_NODES * F1];
__device__ __align__(256) float g_y2[MAX_NODES * F2];
__device__ __align__(256) float g_h2[MAX_NODES * F2];
__device__ __align__(256) float g_y3[MAX_NODES * F3];
__device__ __align__(256) float g_h3[MAX_NODES * F3];
__device__ __align__(256) int   g_cnt[MAX_NODES];         // zero-init; re-zeroed by agg3_softmax
__device__ __align__(256) int   g_slots[MAX_NODES * CAP]; // per-dst src buckets

// ---- PDL device controls ----
__device__ __forceinline__ void pdl_wait()    { asm volatile("griddepcontrol.wait;" ::: "memory"); }
__device__ __forceinline__ void pdl_trigger() { asm volatile("griddepcontrol.launch_dependents;" ::: "memory"); }

// ---- packed f32x2 helpers ----
__device__ __forceinline__ unsigned long long pack2(float lo, float hi) {
    unsigned long long r;
    asm("mov.b64 %0, {%1, %2};" : "=l"(r) : "f"(lo), "f"(hi));
    return r;
}
__device__ __forceinline__ void unpack2(unsigned long long v, float& lo, float& hi) {
    asm("mov.b64 {%0, %1}, %2;" : "=f"(lo), "=f"(hi) : "l"(v));
}
__device__ __forceinline__ unsigned long long ffma2(
    unsigned long long a, unsigned long long b, unsigned long long c) {
    unsigned long long d;
    asm("fma.rn.f32x2 %0, %1, %2, %3;" : "=l"(d) : "l"(a), "l"(b), "l"(c));
    return d;
}

// ---------------------------------------------------------------------------
// Bucket fill. Counters are zero at entry: statically zero-initialized at
// load, and re-zeroed by agg3_softmax_k at the end of every execution.
// ---------------------------------------------------------------------------
__global__ void fill_k(const int* __restrict__ ei, int* __restrict__ cnt,
                       int* __restrict__ slots, int e) {
    int pe = blockIdx.x * blockDim.x + threadIdx.x;
    int base = 4 * pe;
    if (base >= e) return;

    int src[4], dst[4];
    if (base + 3 < e) {
        int4 s4 = __ldg(reinterpret_cast<const int4*>(ei) + pe);
        int4 d4 = __ldg(reinterpret_cast<const int4*>(ei + e) + pe);
        src[0] = s4.x; src[1] = s4.y; src[2] = s4.z; src[3] = s4.w;
        dst[0] = d4.x; dst[1] = d4.y; dst[2] = d4.z; dst[3] = d4.w;
    } else {
#pragma unroll
        for (int i = 0; i < 4; i++) {
            int eid = base + i;
            bool ok = eid < e;
            src[i] = ok ? __ldg(ei + eid) : 0;
            dst[i] = ok ? __ldg(ei + e + eid) : -1;
        }
    }
#pragma unroll
    for (int i = 0; i < 4; i++) {
        if (base + i < e && dst[i] >= 0) {
            int pos = atomicAdd(&cnt[dst[i]], 1);
            if (pos < CAP) slots[dst[i] * CAP + pos] = src[i];
        }
    }
    pdl_trigger();
}

// ---------------------------------------------------------------------------
// Dense transform (R13/R14 exact): y = act(x)@Wrel ; h = act(x)@Wroot + b.
// ---------------------------------------------------------------------------
template <int FIN, int FOUT, bool RELU>
__global__ void transform_k(const float* __restrict__ x,
                            const float* __restrict__ Wrel,
                            const float* __restrict__ Wroot,
                            const float* __restrict__ b,
                            float* __restrict__ y,
                            float* __restrict__ h,
                            int n) {
    __shared__ __align__(16) float s_rel[FIN * FOUT];
    __shared__ __align__(16) float s_root[FIN * FOUT];
    __shared__ float s_b[FOUT];
    for (int i = threadIdx.x; i < FIN * FOUT; i += blockDim.x) {
        s_rel[i]  = Wrel[i];
        s_root[i] = Wroot[i];
    }
    for (int i = threadIdx.x; i < FOUT; i += blockDim.x) s_b[i] = b[i];
    __syncthreads();

    pdl_wait();

    int node = blockIdx.x * blockDim.x + threadIdx.x;
    if (node >= n) { pdl_trigger(); return; }

    constexpr int P = FOUT / 2;
    unsigned long long accR[P], accO[P];
#pragma unroll
    for (int p = 0; p < P; p++) { accR[p] = 0ull; accO[p] = 0ull; }

    const float4* xr = reinterpret_cast<const float4*>(x + (size_t)node * FIN);
#pragma unroll
    for (int kk = 0; kk < FIN / 4; kk++) {
        float4 xv = __ldg(xr + kk);
        float xs[4] = {xv.x, xv.y, xv.z, xv.w};
#pragma unroll
        for (int q = 0; q < 4; q++) {
            float v = RELU ? fmaxf(xs[q], 0.f) : xs[q];
            unsigned long long a = pack2(v, v);
            const int k = kk * 4 + q;
            if constexpr (FOUT >= 4) {
#pragma unroll
                for (int j4 = 0; j4 < FOUT / 4; j4++) {
                    ulonglong2 wr = *reinterpret_cast<const ulonglong2*>(&s_rel[k * FOUT + j4 * 4]);
                    ulonglong2 wo = *reinterpret_cast<const ulonglong2*>(&s_root[k * FOUT + j4 * 4]);
                    accR[j4 * 2 + 0] = ffma2(a, wr.x, accR[j4 * 2 + 0]);
                    accR[j4 * 2 + 1] = ffma2(a, wr.y, accR[j4 * 2 + 1]);
                    accO[j4 * 2 + 0] = ffma2(a, wo.x, accO[j4 * 2 + 0]);
                    accO[j4 * 2 + 1] = ffma2(a, wo.y, accO[j4 * 2 + 1]);
                }
            } else {
                unsigned long long wr = *reinterpret_cast<const unsigned long long*>(&s_rel[k * FOUT]);
                unsigned long long wo = *reinterpret_cast<const unsigned long long*>(&s_root[k * FOUT]);
                accR[0] = ffma2(a, wr, accR[0]);
                accO[0] = ffma2(a, wo, accO[0]);
            }
        }
    }

    float* yo = y + (size_t)node * FOUT;
    float* ho = h + (size_t)node * FOUT;
    float outR[FOUT], outO[FOUT];
#pragma unroll
    for (int p = 0; p < P; p++) {
        unpack2(accR[p], outR[2 * p], outR[2 * p + 1]);
        unpack2(accO[p], outO[2 * p], outO[2 * p + 1]);
    }
    if constexpr (FOUT >= 4) {
#pragma unroll
        for (int j4 = 0; j4 < FOUT / 4; j4++) {
            reinterpret_cast<float4*>(yo)[j4] =
                make_float4(outR[j4 * 4], outR[j4 * 4 + 1], outR[j4 * 4 + 2], outR[j4 * 4 + 3]);
            reinterpret_cast<float4*>(ho)[j4] =
                make_float4(outO[j4 * 4] + s_b[j4 * 4],         outO[j4 * 4 + 1] + s_b[j4 * 4 + 1],
                            outO[j4 * 4 + 2] + s_b[j4 * 4 + 2], outO[j4 * 4 + 3] + s_b[j4 * 4 + 3]);
        }
    } else {
        *reinterpret_cast<float2*>(yo) = make_float2(outR[0], outR[1]);
        *reinterpret_cast<float2*>(ho) = make_float2(outO[0] + s_b[0], outO[1] + s_b[1]);
    }
    pdl_trigger();
}

// ---------------------------------------------------------------------------
// Pull aggregation (R14 exact body, MLP4) + occupancy floor of 6 blocks/SM.
// ---------------------------------------------------------------------------
template <int F>
__global__ void __launch_bounds__(256, 6)
agg_k(const int* __restrict__ cnt, const int* __restrict__ slots,
      const float* __restrict__ y, float* __restrict__ h, int n) {
    constexpr int CH = F / 4;
    pdl_wait();
    int t = blockIdx.x * blockDim.x + threadIdx.x;
    if (t >= n * CH) { pdl_trigger(); return; }
    int node = t / CH;
    int c = t % CH;
    int deg = min(__ldg(cnt + node), CAP);
    const int* sl = slots + node * CAP;

    float4 a0 = make_float4(0.f, 0.f, 0.f, 0.f);
    float4 a1 = a0, a2 = a0, a3 = a0;
    int i = 0;
    for (; i + 4 <= deg; i += 4) {
        int4 q0 = __ldg(reinterpret_cast<const int4*>(sl + i));
        float4 v0 = __ldg(reinterpret_cast<const float4*>(y + (size_t)q0.x * F + c * 4));
        float4 v1 = __ldg(reinterpret_cast<const float4*>(y + (size_t)q0.y * F + c * 4));
        float4 v2 = __ldg(reinterpret_cast<const float4*>(y + (size_t)q0.z * F + c * 4));
        float4 v3 = __ldg(reinterpret_cast<const float4*>(y + (size_t)q0.w * F + c * 4));
        a0.x += v0.x; a0.y += v0.y; a0.z += v0.z; a0.w += v0.w;
        a1.x += v1.x; a1.y += v1.y; a1.z += v1.z; a1.w += v1.w;
        a2.x += v2.x; a2.y += v2.y; a2.z += v2.z; a2.w += v2.w;
        a3.x += v3.x; a3.y += v3.y; a3.z += v3.z; a3.w += v3.w;
    }
    for (; i < deg; i++) {
        int s = __ldg(sl + i);
        float4 v = __ldg(reinterpret_cast<const float4*>(y + (size_t)s * F + c * 4));
        a0.x += v.x; a0.y += v.y; a0.z += v.z; a0.w += v.w;
    }
    float4 acc = make_float4(a0.x + a1.x + a2.x + a3.x,
                             a0.y + a1.y + a2.y + a3.y,
                             a0.z + a1.z + a2.z + a3.z,
                             a0.w + a1.w + a2.w + a3.w);
    float4* hp = reinterpret_cast<float4*>(h + (size_t)node * F) + c;
    float4 r = *hp;
    r.x += acc.x; r.y += acc.y; r.z += acc.z; r.w += acc.w;
    *hp = r;
    pdl_trigger();
}

// Layer-3 pull aggregation (F=2) fused with softmax; resets cnt for the next
// execution (keeps fill_k's precondition without a zero kernel).
__global__ void __launch_bounds__(128, 8)
agg3_softmax_k(int* __restrict__ cnt, const int* __restrict__ slots,
               const float* __restrict__ y, const float* __restrict__ h,
               float* __restrict__ out, int n) {
    pdl_wait();
    int node = blockIdx.x * blockDim.x + threadIdx.x;
    if (node >= n) return;
    int deg = min(cnt[node], CAP);
    cnt[node] = 0;   // reset for next execution (sole final reader of cnt)
    const int* sl = slots + node * CAP;

    float ax0 = 0.f, ay0 = 0.f, ax1 = 0.f, ay1 = 0.f;
    float ax2 = 0.f, ay2 = 0.f, ax3 = 0.f, ay3 = 0.f;
    int i = 0;
    for (; i + 4 <= deg; i += 4) {
        int4 q0 = __ldg(reinterpret_cast<const int4*>(sl + i));
        float2 v0 = __ldg(reinterpret_cast<const float2*>(y + 2 * (size_t)q0.x));
        float2 v1 = __ldg(reinterpret_cast<const float2*>(y + 2 * (size_t)q0.y));
        float2 v2 = __ldg(reinterpret_cast<const float2*>(y + 2 * (size_t)q0.z));
        float2 v3 = __ldg(reinterpret_cast<const float2*>(y + 2 * (size_t)q0.w));
        ax0 += v0.x; ay0 += v0.y;
        ax1 += v1.x; ay1 += v1.y;
        ax2 += v2.x; ay2 += v2.y;
        ax3 += v3.x; ay3 += v3.y;
    }
    for (; i < deg; i++) {
        int s = __ldg(sl + i);
        float2 v = __ldg(reinterpret_cast<const float2*>(y + 2 * (size_t)s));
        ax0 += v.x; ay0 += v.y;
    }
    float ax = (ax0 + ax1) + (ax2 + ax3);
    float ay = (ay0 + ay1) + (ay2 + ay3);

    float2 r = *reinterpret_cast<const float2*>(h + 2 * (size_t)node);
    float vx = r.x + ax, vy = r.y + ay;
    float m  = fmaxf(vx, vy);
    float ea = __expf(vx - m);
    float eb = __expf(vy - m);
    float inv = 1.0f / (ea + eb);
    reinterpret_cast<float2*>(out)[node] = make_float2(ea * inv, eb * inv);
}

// ---------------------------------------------------------------------------
// Host: 7 PDL-chained launches on one stream.
// ---------------------------------------------------------------------------
static void launch_one(const void* fn, int grid, int block, void** args, bool pdl) {
    cudaLaunchConfig_t cfg = {};
    cfg.gridDim = dim3((unsigned)grid, 1, 1);
    cfg.blockDim = dim3((unsigned)block, 1, 1);
    cfg.dynamicSmemBytes = 0;
    cfg.stream = 0;
    cudaLaunchAttribute attr[1];
    if (pdl) {
        attr[0].id = cudaLaunchAttributeProgrammaticStreamSerialization;
        attr[0].val.programmaticStreamSerializationAllowed = 1;
        cfg.attrs = attr;
        cfg.numAttrs = 1;
    }
    cudaLaunchKernelExC(&cfg, fn, args);
}

extern "C" void kernel_launch(void* const* d_in, const int* in_sizes, int n_in,
                              void* d_out, int out_size) {
    const float* z      = (const float*)d_in[0];
    const int*   ei     = (const int*)d_in[1];   // int32 (JAX x64 disabled)
    const float* Wrel1  = (const float*)d_in[2];
    const float* Wroot1 = (const float*)d_in[3];
    const float* b1     = (const float*)d_in[4];
    const float* Wrel2  = (const float*)d_in[5];
    const float* Wroot2 = (const float*)d_in[6];
    const float* b2     = (const float*)d_in[7];
    const float* Wrel3  = (const float*)d_in[8];
    const float* Wroot3 = (const float*)d_in[9];
    const float* b3     = (const float*)d_in[10];

    int n = in_sizes[0] / 64;   // 100000
    int e = in_sizes[1] / 2;    // 1600000

    float *y1, *h1, *y2, *h2, *y3, *h3;
    int *cnt, *slots;
    cudaGetSymbolAddress((void**)&y1, g_y1);
    cudaGetSymbolAddress((void**)&h1, g_h1);
    cudaGetSymbolAddress((void**)&y2, g_y2);
    cudaGetSymbolAddress((void**)&h2, g_h2);
    cudaGetSymbolAddress((void**)&y3, g_y3);
    cudaGetSymbolAddress((void**)&h3, g_h3);
    cudaGetSymbolAddress((void**)&cnt, g_cnt);
    cudaGetSymbolAddress((void**)&slots, g_slots);

    const int TB = 128;
    const int nodeBlocks = (n + TB - 1) / TB;
    const int eq = (e + 3) / 4;
    float* out = (float*)d_out;

    // Bucket fill (counters already zero: static init / reset by agg3_softmax)
    {
        void* args[] = {&ei, &cnt, &slots, &e};
        launch_one((const void*)fill_k, (eq + 255) / 256, 256, args, false);
    }
    // Layer 1
    {
        void* args[] = {&z, &Wrel1, &Wroot1, &b1, &y1, &h1, &n};
        launch_one((const void*)transform_k<64, F1, false>, nodeBlocks, TB, args, true);
    }
    {
        int blocks = (n * (F1 / 4) + 255) / 256;
        void* args[] = {&cnt, &slots, &y1, &h1, &n};
        launch_one((const void*)agg_k<F1>, blocks, 256, args, true);
    }
    // Layer 2
    {
        void* args[] = {&h1, &Wrel2, &Wroot2, &b2, &y2, &h2, &n};
        launch_one((const void*)transform_k<F1, F2, true>, nodeBlocks, TB, args, true);
    }
    {
        int blocks = (n * (F2 / 4) + 255) / 256;
        void* args[] = {&cnt, &slots, &y2, &h2, &n};
        launch_one((const void*)agg_k<F2>, blocks, 256, args, true);
    }
    // Layer 3 + fused softmax (+ counter reset)
    {
        void* args[] = {&h2, &Wrel3, &Wroot3, &b3, &y3, &h3, &n};
        launch_one((const void*)transform_k<F2, F3, true>, nodeBlocks, TB, args, true);
    }
    {
        void* args[] = {&cnt, &slots, &y3, &h3, &out, &n};
        launch_one((const void*)agg3_softmax_k, nodeBlocks, TB, args, true);
    }
}